// round 16
// baseline (speedup 1.0000x reference)
#include <cuda_runtime.h>
#include <cuda_fp16.h>
#include <cstdint>
#include <math.h>

#define BSZ 2
#define SEQ 2048
#define EMB 2048
#define NH 16
#define NKV 4
#define HD 128

typedef __half fp16;

// ---- scratch (static device memory; allocation APIs are forbidden) ----
__device__ fp16 g_xh[BSZ * SEQ * EMB];
__device__ fp16 g_qh[BSZ * SEQ * NH * HD];
__device__ fp16 g_kh[BSZ * SEQ * NKV * HD];
__device__ fp16 g_vh[BSZ * SEQ * NKV * HD];
__device__ fp16 g_ath[BSZ * SEQ * EMB];
__device__ fp16 g_wqth[EMB * EMB];
__device__ fp16 g_wkth[NKV * HD * EMB];
__device__ fp16 g_wvth[NKV * HD * EMB];
__device__ fp16 g_woth[EMB * EMB];

// ============================================================================
// warp-mma helpers
// ============================================================================
__device__ __forceinline__ uint32_t smem_u32(const void* p) {
    uint32_t a;
    asm("{ .reg .u64 t; cvta.to.shared.u64 t, %1; cvt.u32.u64 %0, t; }" : "=r"(a) : "l"(p));
    return a;
}
__device__ __forceinline__ void mma_fp16(float* c, const uint32_t* a, const uint32_t* b) {
    asm("mma.sync.aligned.m16n8k16.row.col.f32.f16.f16.f32 "
        "{%0,%1,%2,%3}, {%4,%5,%6,%7}, {%8,%9}, {%0,%1,%2,%3};"
        : "+f"(c[0]), "+f"(c[1]), "+f"(c[2]), "+f"(c[3])
        : "r"(a[0]), "r"(a[1]), "r"(a[2]), "r"(a[3]), "r"(b[0]), "r"(b[1]));
}
__device__ __forceinline__ void ldsm4(uint32_t* r, uint32_t addr) {
    asm volatile("ldmatrix.sync.aligned.m8n8.x4.shared.b16 {%0,%1,%2,%3}, [%4];"
                 : "=r"(r[0]), "=r"(r[1]), "=r"(r[2]), "=r"(r[3]) : "r"(addr));
}
__device__ __forceinline__ void ldsm4t(uint32_t* r, uint32_t addr) {
    asm volatile("ldmatrix.sync.aligned.m8n8.x4.trans.shared.b16 {%0,%1,%2,%3}, [%4];"
                 : "=r"(r[0]), "=r"(r[1]), "=r"(r[2]), "=r"(r[3]) : "r"(addr));
}
__device__ __forceinline__ uint32_t pack2h(fp16 lo, fp16 hi) {
    __half2 t = __halves2half2(lo, hi);
    return *reinterpret_cast<uint32_t*>(&t);
}
// cp.async 16B
__device__ __forceinline__ void cpa16(uint32_t s, const void* g) {
    asm volatile("cp.async.cg.shared.global [%0], [%1], 16;" :: "r"(s), "l"(g));
}
__device__ __forceinline__ void cpa_commit() { asm volatile("cp.async.commit_group;" ::: "memory"); }
__device__ __forceinline__ void cpa_wait0()  { asm volatile("cp.async.wait_group 0;" ::: "memory"); }

// ============================================================================
// Round fp32 -> fp16 (elementwise)
// ============================================================================
__global__ void around_k(const float* __restrict__ A, fp16* __restrict__ H, int n)
{
    int i = blockIdx.x * blockDim.x + threadIdx.x;
    if (i >= n) return;
    H[i] = __float2half_rn(A[i]);
}

// ============================================================================
// Transpose + round: W[K,N] fp32 -> Th[N,K] fp16
// ============================================================================
__global__ void wsplit_t_k(const float* __restrict__ W, fp16* __restrict__ Th,
                           int K, int N)
{
    __shared__ float t[32][33];
    int n0 = blockIdx.x * 32, k0 = blockIdx.y * 32;
    int tx = threadIdx.x, ty = threadIdx.y;  // 32 x 8
#pragma unroll
    for (int j = 0; j < 32; j += 8)
        t[ty + j][tx] = W[(size_t)(k0 + ty + j) * N + n0 + tx];
    __syncthreads();
#pragma unroll
    for (int j = 0; j < 32; j += 8) {
        size_t o = (size_t)(n0 + ty + j) * K + k0 + tx;
        Th[o] = __float2half_rn(t[tx][ty + j]);
    }
}

// ============================================================================
// fp16 GEMM on mma.sync + cp.async 2-stage pipeline (single product).
// C = Ah[M,K] x Bh[N,K]^T.  Output modes:
//   OUT_F32    : fp32 row-major
//   OUT_H      : fp16 (round)
//   OUT_H_ROPE : fp16 with fused RoPE (epilogue col pair == rope pair)
// ============================================================================
#define OUT_F32 0
#define OUT_H 1
#define OUT_H_ROPE 2
#define GSTR 40                         // row stride elems (80B, 16B-aligned)

template <int BN, int OMODE>
__global__ __launch_bounds__(256) void gemm_mma(const fp16* __restrict__ Ah,
                                                const fp16* __restrict__ Bh,
                                                void* __restrict__ Cout,
                                                int M, int N, int K,
                                                const float* __restrict__ cs,
                                                const float* __restrict__ sn)
{
    constexpr int NT = BN / 32;                 // n-tiles (8 cols) per warp
    constexpr int STG = (128 + BN) * GSTR;      // stage elems
    constexpr int BH_OFF = 128 * GSTR;

    extern __shared__ fp16 gsm[];

    const int tid = threadIdx.x, lane = tid & 31, warp = tid >> 5;
    const int wm = warp >> 2;              // 0..1 -> M offset wm*64
    const int wn = warp & 3;               // 0..3 -> N offset wn*(BN/4)
    const int mB = blockIdx.y * 128, nB = blockIdx.x * BN;

    float c[4][NT][4];
#pragma unroll
    for (int i = 0; i < 4; i++)
#pragma unroll
        for (int j = 0; j < NT; j++)
#pragma unroll
            for (int e = 0; e < 4; e++) c[i][j][e] = 0.f;

    auto copy_stage = [&](int kk, int st) {
        fp16* sb = gsm + st * STG;
#pragma unroll
        for (int j = 0; j < 2; j++) {
            int ch = tid + j * 256;
            int r = ch >> 2, kc8 = (ch & 3) * 8;
            uint32_t sa = smem_u32(sb + r * GSTR + kc8);
            size_t ga = (size_t)(mB + r) * K + kk + kc8;
            cpa16(sa, &Ah[ga]);
        }
#pragma unroll
        for (int j = 0; j < BN / 64; j++) {
            int ch = tid + j * 256;
            int r = ch >> 2, kc8 = (ch & 3) * 8;
            uint32_t sa = smem_u32(sb + BH_OFF + r * GSTR + kc8);
            size_t gb = (size_t)(nB + r) * K + kk + kc8;
            cpa16(sa, &Bh[gb]);
        }
    };

    const int nk = K / 32;
    copy_stage(0, 0);
    cpa_commit();

    for (int i = 0; i < nk; i++) {
        cpa_wait0();
        __syncthreads();
        if (i + 1 < nk) { copy_stage((i + 1) * 32, (i + 1) & 1); cpa_commit(); }

        fp16* sb = gsm + (i & 1) * STG;
        fp16* sAh_ = sb;
        fp16* sBh_ = sb + BH_OFF;

#pragma unroll
        for (int ks = 0; ks < 2; ks++) {
            uint32_t fAh[4][4], fBh[NT / 2][4];
#pragma unroll
            for (int mt = 0; mt < 4; mt++) {
                int e = (wm * 64 + mt * 16 + (lane & 15)) * GSTR + ks * 16 + (lane >> 4) * 8;
                ldsm4(fAh[mt], smem_u32(&sAh_[e]));
            }
            {
                const int m = lane >> 3;
#pragma unroll
                for (int p = 0; p < NT / 2; p++) {
                    int e = (wn * (BN / 4) + p * 16 + (m >> 1) * 8 + (lane & 7)) * GSTR
                          + ks * 16 + (m & 1) * 8;
                    ldsm4(fBh[p], smem_u32(&sBh_[e]));
                }
            }
#pragma unroll
            for (int mt = 0; mt < 4; mt++)
#pragma unroll
                for (int nt = 0; nt < NT; nt++)
                    mma_fp16(c[mt][nt], fAh[mt], &fBh[nt >> 1][(nt & 1) * 2]);
        }
    }

    // epilogue
#pragma unroll
    for (int mt = 0; mt < 4; mt++)
#pragma unroll
        for (int nt = 0; nt < NT; nt++) {
            int row = mB + wm * 64 + mt * 16 + (lane >> 2);
            int col = nB + wn * (BN / 4) + nt * 8 + (lane & 3) * 2;
            float* cc = c[mt][nt];
            if (OMODE == OUT_F32) {
                float* C = (float*)Cout;
                float2 v0 = {cc[0], cc[1]};
                float2 v1 = {cc[2], cc[3]};
                *(float2*)&C[(size_t)row * N + col] = v0;
                *(float2*)&C[(size_t)(row + 8) * N + col] = v1;
            } else if (OMODE == OUT_H) {
                fp16* C = (fp16*)Cout;
                *(uint32_t*)&C[(size_t)row * N + col] =
                    pack2h(__float2half_rn(cc[0]), __float2half_rn(cc[1]));
                *(uint32_t*)&C[(size_t)(row + 8) * N + col] =
                    pack2h(__float2half_rn(cc[2]), __float2half_rn(cc[3]));
            } else {
                // fused RoPE: (col, col+1) is an interleaved rope pair
                fp16* C = (fp16*)Cout;
                int p = (col & (HD - 1)) >> 1;
                int s0 = row & (SEQ - 1), s8 = (row + 8) & (SEQ - 1);
                float c0 = cs[s0 * 64 + p], i0 = sn[s0 * 64 + p];
                float c8 = cs[s8 * 64 + p], i8 = sn[s8 * 64 + p];
                float r0 = cc[0] * c0 - cc[1] * i0;
                float m0 = cc[0] * i0 + cc[1] * c0;
                float r8 = cc[2] * c8 - cc[3] * i8;
                float m8 = cc[2] * i8 + cc[3] * c8;
                *(uint32_t*)&C[(size_t)row * N + col] =
                    pack2h(__float2half_rn(r0), __float2half_rn(m0));
                *(uint32_t*)&C[(size_t)(row + 8) * N + col] =
                    pack2h(__float2half_rn(r8), __float2half_rn(m8));
            }
        }
}

#define GEMM_SMEM_256 (2 * (128 + 256) * GSTR * 2)   // 61440 B
#define GEMM_SMEM_128 (2 * (128 + 128) * GSTR * 2)   // 40960 B

// ============================================================================
// Flash attention on mma.sync. Single-stage KV buffer (69.6 KB smem) +
// __launch_bounds__(256, 2) -> 2 CTAs/SM; the co-resident CTA fills softmax
// bubbles and covers KV-load latency (replaces in-CTA double buffering).
// S = Qh Kh^T (1 product).  O += Ph Vh (1 product).  Output fp16.
// Numerically identical to the R14 kernel.
// ============================================================================
#define FSTR 136                       // 128 + 8 pad (272B rows)
#define FQ 0
#define KVBASE (128 * FSTR)
#define FV_OFF (64 * FSTR)             // elem offset of V within KV buffer
#define FSM_ELEMS (KVBASE + 2 * 64 * FSTR) // 34816 elems = 69632 B

__global__ __launch_bounds__(256, 2) void flash_mma(const fp16* __restrict__ Qh,
                                                    const fp16* __restrict__ Kh,
                                                    const fp16* __restrict__ Vh,
                                                    fp16* __restrict__ Oh)
{
    extern __shared__ fp16 fsm[];
    const int tid = threadIdx.x, lane = tid & 31, warp = tid >> 5;
    const int qt = (gridDim.x - 1) - blockIdx.x;   // heavy tiles first
    const int h = blockIdx.y, b = blockIdx.z;
    const int q0 = qt * 128;
    const int khead = h >> 2;
    const float scale = 0.08838834764831845f;

    // load Q tile (128 x 128)
    for (int cidx = tid; cidx < 2048; cidx += 256) {
        int row = cidx >> 4, kc = (cidx & 15) * 8;
        size_t g = (size_t)(b * SEQ + q0 + row) * (NH * HD) + h * HD + kc;
        *(uint4*)&fsm[FQ + row * FSTR + kc] = *(const uint4*)&Qh[g];
    }

    auto copy_kv = [&](int t) {
        const int k0 = t * 64;
        const size_t gbase = (size_t)(b * SEQ + k0) * (NKV * HD) + khead * HD;
        uint32_t s0 = smem_u32(fsm + KVBASE);
#pragma unroll
        for (int j = 0; j < 4; j++) {
            int ch = tid + j * 256;
            int r = ch >> 4, kc8 = (ch & 15) * 8;
            size_t g = gbase + (size_t)r * (NKV * HD) + kc8;
            uint32_t so = (uint32_t)(r * FSTR + kc8) * 2;
            cpa16(s0 + so,              &Kh[g]);
            cpa16(s0 + FV_OFF * 2 + so, &Vh[g]);
        }
    };

    float o[16][4];
#pragma unroll
    for (int i = 0; i < 16; i++)
#pragma unroll
        for (int e = 0; e < 4; e++) o[i][e] = 0.f;
    float mrow[2] = {-1e30f, -1e30f}, lrow[2] = {0.f, 0.f};

    const int ntiles = 2 * qt + 2;

    for (int t = 0; t < ntiles; t++) {
        __syncthreads();               // all readers of previous KV tile done
        copy_kv(t);
        cpa_commit();
        cpa_wait0();
        __syncthreads();               // KV tile visible to all warps

        const int k0 = t * 64;
        fp16* sKH = fsm + KVBASE;
        fp16* sVH = sKH + FV_OFF;

        // ---- S = Qh Kh^T ----
        float s[8][4];
#pragma unroll
        for (int i = 0; i < 8; i++)
#pragma unroll
            for (int e = 0; e < 4; e++) s[i][e] = 0.f;

#pragma unroll
        for (int ks = 0; ks < 8; ks++) {
            uint32_t qf[4];
            int qa = (warp * 16 + (lane & 15)) * FSTR + ks * 16 + (lane >> 4) * 8;
            ldsm4(qf, smem_u32(&fsm[FQ + qa]));
            const int m = lane >> 3;
#pragma unroll
            for (int p = 0; p < 4; p++) {
                uint32_t kb[4];
                int ka = (p * 16 + (m >> 1) * 8 + (lane & 7)) * FSTR + ks * 16 + (m & 1) * 8;
                ldsm4(kb, smem_u32(&sKH[ka]));
                mma_fp16(s[p * 2],     qf, &kb[0]);
                mma_fp16(s[p * 2 + 1], qf, &kb[2]);
            }
        }

        // ---- scale + causal mask ----
        const int r0 = q0 + warp * 16 + (lane >> 2);
        const bool needmask = (t >= ntiles - 2);
#pragma unroll
        for (int nt = 0; nt < 8; nt++) {
#pragma unroll
            for (int e = 0; e < 4; e++) {
                float v = s[nt][e] * scale;
                if (needmask) {
                    int col = k0 + nt * 8 + (lane & 3) * 2 + (e & 1);
                    int row = r0 + ((e >> 1) << 3);
                    if (col > row) v = -1e30f;
                }
                s[nt][e] = v;
            }
        }

        // ---- online softmax ----
        float mx0 = -1e30f, mx1 = -1e30f;
#pragma unroll
        for (int nt = 0; nt < 8; nt++) {
            mx0 = fmaxf(mx0, fmaxf(s[nt][0], s[nt][1]));
            mx1 = fmaxf(mx1, fmaxf(s[nt][2], s[nt][3]));
        }
        mx0 = fmaxf(mx0, __shfl_xor_sync(0xffffffff, mx0, 1));
        mx0 = fmaxf(mx0, __shfl_xor_sync(0xffffffff, mx0, 2));
        mx1 = fmaxf(mx1, __shfl_xor_sync(0xffffffff, mx1, 1));
        mx1 = fmaxf(mx1, __shfl_xor_sync(0xffffffff, mx1, 2));
        float mn0 = fmaxf(mrow[0], mx0), mn1 = fmaxf(mrow[1], mx1);
        float f0 = __expf(mrow[0] - mn0), f1 = __expf(mrow[1] - mn1);

        float sum0 = 0.f, sum1 = 0.f;
#pragma unroll
        for (int nt = 0; nt < 8; nt++) {
            s[nt][0] = __expf(s[nt][0] - mn0);
            s[nt][1] = __expf(s[nt][1] - mn0);
            s[nt][2] = __expf(s[nt][2] - mn1);
            s[nt][3] = __expf(s[nt][3] - mn1);
            sum0 += s[nt][0] + s[nt][1];
            sum1 += s[nt][2] + s[nt][3];
        }
        sum0 += __shfl_xor_sync(0xffffffff, sum0, 1);
        sum0 += __shfl_xor_sync(0xffffffff, sum0, 2);
        sum1 += __shfl_xor_sync(0xffffffff, sum1, 1);
        sum1 += __shfl_xor_sync(0xffffffff, sum1, 2);
        lrow[0] = lrow[0] * f0 + sum0;
        lrow[1] = lrow[1] * f1 + sum1;
        mrow[0] = mn0;
        mrow[1] = mn1;

        // ---- rescale O ----
#pragma unroll
        for (int nt = 0; nt < 16; nt++) {
            o[nt][0] *= f0; o[nt][1] *= f0;
            o[nt][2] *= f1; o[nt][3] *= f1;
        }

        // ---- O += Ph Vh ----
#pragma unroll
        for (int ks = 0; ks < 4; ks++) {
            uint32_t ph[4];
#pragma unroll
            for (int half = 0; half < 2; half++) {
                int ti2 = 2 * ks + half;
                ph[2 * half]     = pack2h(__float2half_rn(s[ti2][0]), __float2half_rn(s[ti2][1]));
                ph[2 * half + 1] = pack2h(__float2half_rn(s[ti2][2]), __float2half_rn(s[ti2][3]));
            }
            const int m = lane >> 3;
#pragma unroll
            for (int pp = 0; pp < 8; pp++) {
                uint32_t vf[4];
                int va = (ks * 16 + (m & 1) * 8 + (lane & 7)) * FSTR + (pp * 2 + (m >> 1)) * 8;
                ldsm4t(vf, smem_u32(&sVH[va]));
                mma_fp16(o[pp * 2],     ph, &vf[0]);
                mma_fp16(o[pp * 2 + 1], ph, &vf[2]);
            }
        }
    }

    // ---- finalize: divide by l, write fp16 ----
    float inv0 = 1.f / lrow[0], inv1 = 1.f / lrow[1];
    const size_t tok0 = (size_t)(b * SEQ + q0 + warp * 16 + (lane >> 2));
#pragma unroll
    for (int nt = 0; nt < 16; nt++) {
        int col = h * HD + nt * 8 + (lane & 3) * 2;
        size_t a0 = tok0 * EMB + col;
        size_t a1 = (tok0 + 8) * EMB + col;
        *(uint32_t*)&Oh[a0] = pack2h(__float2half_rn(o[nt][0] * inv0),
                                     __float2half_rn(o[nt][1] * inv0));
        *(uint32_t*)&Oh[a1] = pack2h(__float2half_rn(o[nt][2] * inv1),
                                     __float2half_rn(o[nt][3] * inv1));
    }
}

// ============================================================================
// launch
// ============================================================================
extern "C" void kernel_launch(void* const* d_in, const int* in_sizes, int n_in,
                              void* d_out, int out_size)
{
    const float* x  = (const float*)d_in[0];
    const float* cs = (const float*)d_in[1];
    const float* sn = (const float*)d_in[2];
    const float* wq = (const float*)d_in[3];
    const float* wk = (const float*)d_in[4];
    const float* wv = (const float*)d_in[5];
    const float* wo = (const float*)d_in[6];
    float* out = (float*)d_out;

    fp16 *xh, *qh, *kh, *vh, *ath;
    fp16 *wqth, *wkth, *wvth, *woth;
    cudaGetSymbolAddress((void**)&xh,  g_xh);
    cudaGetSymbolAddress((void**)&qh,  g_qh);
    cudaGetSymbolAddress((void**)&kh,  g_kh);
    cudaGetSymbolAddress((void**)&vh,  g_vh);
    cudaGetSymbolAddress((void**)&ath, g_ath);
    cudaGetSymbolAddress((void**)&wqth, g_wqth);
    cudaGetSymbolAddress((void**)&wkth, g_wkth);
    cudaGetSymbolAddress((void**)&wvth, g_wvth);
    cudaGetSymbolAddress((void**)&woth, g_woth);

    const int fsmem = FSM_ELEMS * (int)sizeof(fp16);   // 69632 B
    cudaFuncSetAttribute(flash_mma, cudaFuncAttributeMaxDynamicSharedMemorySize, fsmem);
    cudaFuncSetAttribute(gemm_mma<256, OUT_H_ROPE>, cudaFuncAttributeMaxDynamicSharedMemorySize, GEMM_SMEM_256);
    cudaFuncSetAttribute(gemm_mma<256, OUT_F32>,    cudaFuncAttributeMaxDynamicSharedMemorySize, GEMM_SMEM_256);
    cudaFuncSetAttribute(gemm_mma<128, OUT_H_ROPE>, cudaFuncAttributeMaxDynamicSharedMemorySize, GEMM_SMEM_128);
    cudaFuncSetAttribute(gemm_mma<128, OUT_H>,      cudaFuncAttributeMaxDynamicSharedMemorySize, GEMM_SMEM_128);

    const int M = BSZ * SEQ;   // 4096
    const int NKVD = NKV * HD; // 512

    // weight rounds, activation round
    wsplit_t_k<<<dim3(EMB / 32, EMB / 32),  dim3(32, 8)>>>(wq, wqth, EMB, EMB);
    wsplit_t_k<<<dim3(NKVD / 32, EMB / 32), dim3(32, 8)>>>(wk, wkth, EMB, NKVD);
    wsplit_t_k<<<dim3(NKVD / 32, EMB / 32), dim3(32, 8)>>>(wv, wvth, EMB, NKVD);
    wsplit_t_k<<<dim3(EMB / 32, EMB / 32),  dim3(32, 8)>>>(wo, woth, EMB, EMB);
    around_k<<<(M * EMB + 255) / 256, 256>>>(x, xh, M * EMB);

    // QKV projections with fused rope/round epilogues (tensor cores)
    gemm_mma<256, OUT_H_ROPE><<<dim3(EMB / 256, M / 128), 256, GEMM_SMEM_256>>>(
        xh, wqth, qh, M, EMB, EMB, cs, sn);
    gemm_mma<128, OUT_H_ROPE><<<dim3(NKVD / 128, M / 128), 256, GEMM_SMEM_128>>>(
        xh, wkth, kh, M, NKVD, EMB, cs, sn);
    gemm_mma<128, OUT_H><<<dim3(NKVD / 128, M / 128), 256, GEMM_SMEM_128>>>(
        xh, wvth, vh, M, NKVD, EMB, nullptr, nullptr);

    // attention (tensor cores), writes fp16 output
    flash_mma<<<dim3(SEQ / 128, NH, BSZ), 256, fsmem>>>(qh, kh, vh, ath);

    // out projection (tensor cores)
    gemm_mma<256, OUT_F32><<<dim3(EMB / 256, M / 128), 256, GEMM_SMEM_256>>>(
        ath, woth, out, M, EMB, EMB, nullptr, nullptr);
}

// round 17
// speedup vs baseline: 1.6504x; 1.6504x over previous
#include <cuda_runtime.h>
#include <cuda_fp16.h>
#include <cstdint>
#include <math.h>

#define BSZ 2
#define SEQ 2048
#define EMB 2048
#define NH 16
#define NKV 4
#define HD 128

typedef __half fp16;

// ---- scratch (static device memory; allocation APIs are forbidden) ----
__device__ fp16 g_xh[BSZ * SEQ * EMB];
__device__ fp16 g_qh[BSZ * SEQ * NH * HD];
__device__ fp16 g_kh[BSZ * SEQ * NKV * HD];
__device__ fp16 g_vh[BSZ * SEQ * NKV * HD];
__device__ fp16 g_ath[BSZ * SEQ * EMB];
__device__ fp16 g_wqth[EMB * EMB];
__device__ fp16 g_wkth[NKV * HD * EMB];
__device__ fp16 g_wvth[NKV * HD * EMB];
__device__ fp16 g_woth[EMB * EMB];

// ============================================================================
// warp-mma helpers
// ============================================================================
__device__ __forceinline__ uint32_t smem_u32(const void* p) {
    uint32_t a;
    asm("{ .reg .u64 t; cvta.to.shared.u64 t, %1; cvt.u32.u64 %0, t; }" : "=r"(a) : "l"(p));
    return a;
}
__device__ __forceinline__ void mma_fp16(float* c, const uint32_t* a, const uint32_t* b) {
    asm("mma.sync.aligned.m16n8k16.row.col.f32.f16.f16.f32 "
        "{%0,%1,%2,%3}, {%4,%5,%6,%7}, {%8,%9}, {%0,%1,%2,%3};"
        : "+f"(c[0]), "+f"(c[1]), "+f"(c[2]), "+f"(c[3])
        : "r"(a[0]), "r"(a[1]), "r"(a[2]), "r"(a[3]), "r"(b[0]), "r"(b[1]));
}
__device__ __forceinline__ void ldsm4(uint32_t* r, uint32_t addr) {
    asm volatile("ldmatrix.sync.aligned.m8n8.x4.shared.b16 {%0,%1,%2,%3}, [%4];"
                 : "=r"(r[0]), "=r"(r[1]), "=r"(r[2]), "=r"(r[3]) : "r"(addr));
}
__device__ __forceinline__ void ldsm4t(uint32_t* r, uint32_t addr) {
    asm volatile("ldmatrix.sync.aligned.m8n8.x4.trans.shared.b16 {%0,%1,%2,%3}, [%4];"
                 : "=r"(r[0]), "=r"(r[1]), "=r"(r[2]), "=r"(r[3]) : "r"(addr));
}
__device__ __forceinline__ uint32_t pack2h(fp16 lo, fp16 hi) {
    __half2 t = __halves2half2(lo, hi);
    return *reinterpret_cast<uint32_t*>(&t);
}
// cp.async 16B
__device__ __forceinline__ void cpa16(uint32_t s, const void* g) {
    asm volatile("cp.async.cg.shared.global [%0], [%1], 16;" :: "r"(s), "l"(g));
}
__device__ __forceinline__ void cpa_commit() { asm volatile("cp.async.commit_group;" ::: "memory"); }
__device__ __forceinline__ void cpa_wait0()  { asm volatile("cp.async.wait_group 0;" ::: "memory"); }

// ============================================================================
// Round fp32 -> fp16 (elementwise)
// ============================================================================
__global__ void around_k(const float* __restrict__ A, fp16* __restrict__ H, int n)
{
    int i = blockIdx.x * blockDim.x + threadIdx.x;
    if (i >= n) return;
    H[i] = __float2half_rn(A[i]);
}

// ============================================================================
// Transpose + round: W[K,N] fp32 -> Th[N,K] fp16
// ============================================================================
__global__ void wsplit_t_k(const float* __restrict__ W, fp16* __restrict__ Th,
                           int K, int N)
{
    __shared__ float t[32][33];
    int n0 = blockIdx.x * 32, k0 = blockIdx.y * 32;
    int tx = threadIdx.x, ty = threadIdx.y;  // 32 x 8
#pragma unroll
    for (int j = 0; j < 32; j += 8)
        t[ty + j][tx] = W[(size_t)(k0 + ty + j) * N + n0 + tx];
    __syncthreads();
#pragma unroll
    for (int j = 0; j < 32; j += 8) {
        size_t o = (size_t)(n0 + ty + j) * K + k0 + tx;
        Th[o] = __float2half_rn(t[tx][ty + j]);
    }
}

// ============================================================================
// fp16 GEMM on mma.sync + cp.async 2-stage pipeline (single product).
// C = Ah[M,K] x Bh[N,K]^T.  Output modes:
//   OUT_F32    : fp32 row-major
//   OUT_H      : fp16 (round)
//   OUT_H_ROPE : fp16 with fused RoPE (epilogue col pair == rope pair)
//   OUT_KV     : gridDim.z=2; z=0 -> rope to Cout (K-proj), z=1 -> plain fp16
//                to Cout2 from Bh2 (V-proj). One launch fills the machine.
// ============================================================================
#define OUT_F32 0
#define OUT_H 1
#define OUT_H_ROPE 2
#define OUT_KV 3
#define GSTR 40                         // row stride elems (80B, 16B-aligned)

template <int BN, int OMODE>
__global__ __launch_bounds__(256) void gemm_mma(const fp16* __restrict__ Ah,
                                                const fp16* __restrict__ Bh,
                                                const fp16* __restrict__ Bh2,
                                                void* __restrict__ Cout,
                                                void* __restrict__ Cout2,
                                                int M, int N, int K,
                                                const float* __restrict__ cs,
                                                const float* __restrict__ sn)
{
    constexpr int NT = BN / 32;                 // n-tiles (8 cols) per warp
    constexpr int STG = (128 + BN) * GSTR;      // stage elems
    constexpr int BH_OFF = 128 * GSTR;

    extern __shared__ fp16 gsm[];

    const int tid = threadIdx.x, lane = tid & 31, warp = tid >> 5;
    const int wm = warp >> 2;              // 0..1 -> M offset wm*64
    const int wn = warp & 3;               // 0..3 -> N offset wn*(BN/4)
    const int mB = blockIdx.y * 128, nB = blockIdx.x * BN;
    const bool isV = (OMODE == OUT_KV) && (blockIdx.z == 1);
    const fp16* Bsel = isV ? Bh2 : Bh;

    float c[4][NT][4];
#pragma unroll
    for (int i = 0; i < 4; i++)
#pragma unroll
        for (int j = 0; j < NT; j++)
#pragma unroll
            for (int e = 0; e < 4; e++) c[i][j][e] = 0.f;

    auto copy_stage = [&](int kk, int st) {
        fp16* sb = gsm + st * STG;
#pragma unroll
        for (int j = 0; j < 2; j++) {
            int ch = tid + j * 256;
            int r = ch >> 2, kc8 = (ch & 3) * 8;
            uint32_t sa = smem_u32(sb + r * GSTR + kc8);
            size_t ga = (size_t)(mB + r) * K + kk + kc8;
            cpa16(sa, &Ah[ga]);
        }
#pragma unroll
        for (int j = 0; j < BN / 64; j++) {
            int ch = tid + j * 256;
            int r = ch >> 2, kc8 = (ch & 3) * 8;
            uint32_t sa = smem_u32(sb + BH_OFF + r * GSTR + kc8);
            size_t gb = (size_t)(nB + r) * K + kk + kc8;
            cpa16(sa, &Bsel[gb]);
        }
    };

    const int nk = K / 32;
    copy_stage(0, 0);
    cpa_commit();

    for (int i = 0; i < nk; i++) {
        cpa_wait0();
        __syncthreads();
        if (i + 1 < nk) { copy_stage((i + 1) * 32, (i + 1) & 1); cpa_commit(); }

        fp16* sb = gsm + (i & 1) * STG;
        fp16* sAh_ = sb;
        fp16* sBh_ = sb + BH_OFF;

#pragma unroll
        for (int ks = 0; ks < 2; ks++) {
            uint32_t fAh[4][4], fBh[NT / 2][4];
#pragma unroll
            for (int mt = 0; mt < 4; mt++) {
                int e = (wm * 64 + mt * 16 + (lane & 15)) * GSTR + ks * 16 + (lane >> 4) * 8;
                ldsm4(fAh[mt], smem_u32(&sAh_[e]));
            }
            {
                const int m = lane >> 3;
#pragma unroll
                for (int p = 0; p < NT / 2; p++) {
                    int e = (wn * (BN / 4) + p * 16 + (m >> 1) * 8 + (lane & 7)) * GSTR
                          + ks * 16 + (m & 1) * 8;
                    ldsm4(fBh[p], smem_u32(&sBh_[e]));
                }
            }
#pragma unroll
            for (int mt = 0; mt < 4; mt++)
#pragma unroll
                for (int nt = 0; nt < NT; nt++)
                    mma_fp16(c[mt][nt], fAh[mt], &fBh[nt >> 1][(nt & 1) * 2]);
        }
    }

    // epilogue
#pragma unroll
    for (int mt = 0; mt < 4; mt++)
#pragma unroll
        for (int nt = 0; nt < NT; nt++) {
            int row = mB + wm * 64 + mt * 16 + (lane >> 2);
            int col = nB + wn * (BN / 4) + nt * 8 + (lane & 3) * 2;
            float* cc = c[mt][nt];
            if (OMODE == OUT_F32) {
                float* C = (float*)Cout;
                float2 v0 = {cc[0], cc[1]};
                float2 v1 = {cc[2], cc[3]};
                *(float2*)&C[(size_t)row * N + col] = v0;
                *(float2*)&C[(size_t)(row + 8) * N + col] = v1;
            } else if (OMODE == OUT_H || (OMODE == OUT_KV && isV)) {
                fp16* C = (fp16*)(OMODE == OUT_KV ? Cout2 : Cout);
                *(uint32_t*)&C[(size_t)row * N + col] =
                    pack2h(__float2half_rn(cc[0]), __float2half_rn(cc[1]));
                *(uint32_t*)&C[(size_t)(row + 8) * N + col] =
                    pack2h(__float2half_rn(cc[2]), __float2half_rn(cc[3]));
            } else {
                // fused RoPE: (col, col+1) is an interleaved rope pair
                fp16* C = (fp16*)Cout;
                int p = (col & (HD - 1)) >> 1;
                int s0 = row & (SEQ - 1), s8 = (row + 8) & (SEQ - 1);
                float c0 = cs[s0 * 64 + p], i0 = sn[s0 * 64 + p];
                float c8 = cs[s8 * 64 + p], i8 = sn[s8 * 64 + p];
                float r0 = cc[0] * c0 - cc[1] * i0;
                float m0 = cc[0] * i0 + cc[1] * c0;
                float r8 = cc[2] * c8 - cc[3] * i8;
                float m8 = cc[2] * i8 + cc[3] * c8;
                *(uint32_t*)&C[(size_t)row * N + col] =
                    pack2h(__float2half_rn(r0), __float2half_rn(m0));
                *(uint32_t*)&C[(size_t)(row + 8) * N + col] =
                    pack2h(__float2half_rn(r8), __float2half_rn(m8));
            }
        }
}

#define GEMM_SMEM_256 (2 * (128 + 256) * GSTR * 2)   // 61440 B
#define GEMM_SMEM_128 (2 * (128 + 128) * GSTR * 2)   // 40960 B

// ============================================================================
// Flash attention on mma.sync, cp.async 2-stage KV pipeline (R14 version —
// the proven 624.5us configuration, restored verbatim).
// S = Qh Kh^T (1 product).  O += Ph Vh (1 product).  Output fp16.
// ============================================================================
#define FSTR 136                       // 128 + 8 pad (272B rows)
#define FQ 0
#define KVBASE (128 * FSTR)
#define KVSTG (2 * 64 * FSTR)
#define FV_B (64 * FSTR * 2)           // byte offset of V within stage
#define FSM_ELEMS (KVBASE + 2 * KVSTG) // 52224 elems = 104448 B

__global__ __launch_bounds__(256) void flash_mma(const fp16* __restrict__ Qh,
                                                 const fp16* __restrict__ Kh,
                                                 const fp16* __restrict__ Vh,
                                                 fp16* __restrict__ Oh)
{
    extern __shared__ fp16 fsm[];
    const int tid = threadIdx.x, lane = tid & 31, warp = tid >> 5;
    const int qt = (gridDim.x - 1) - blockIdx.x;   // heavy tiles first
    const int h = blockIdx.y, b = blockIdx.z;
    const int q0 = qt * 128;
    const int khead = h >> 2;
    const float scale = 0.08838834764831845f;

    // load Q tile (128 x 128)
    for (int cidx = tid; cidx < 2048; cidx += 256) {
        int row = cidx >> 4, kc = (cidx & 15) * 8;
        size_t g = (size_t)(b * SEQ + q0 + row) * (NH * HD) + h * HD + kc;
        *(uint4*)&fsm[FQ + row * FSTR + kc] = *(const uint4*)&Qh[g];
    }

    auto copy_kv = [&](int t, int st) {
        const int k0 = t * 64;
        const size_t gbase = (size_t)(b * SEQ + k0) * (NKV * HD) + khead * HD;
        uint32_t s0 = smem_u32(fsm + KVBASE + st * KVSTG);
#pragma unroll
        for (int j = 0; j < 4; j++) {
            int ch = tid + j * 256;
            int r = ch >> 4, kc8 = (ch & 15) * 8;
            size_t g = gbase + (size_t)r * (NKV * HD) + kc8;
            uint32_t so = (uint32_t)(r * FSTR + kc8) * 2;
            cpa16(s0 + so,        &Kh[g]);
            cpa16(s0 + FV_B + so, &Vh[g]);
        }
    };

    float o[16][4];
#pragma unroll
    for (int i = 0; i < 16; i++)
#pragma unroll
        for (int e = 0; e < 4; e++) o[i][e] = 0.f;
    float mrow[2] = {-1e30f, -1e30f}, lrow[2] = {0.f, 0.f};

    const int ntiles = 2 * qt + 2;
    copy_kv(0, 0);
    cpa_commit();

    for (int t = 0; t < ntiles; t++) {
        cpa_wait0();
        __syncthreads();
        if (t + 1 < ntiles) { copy_kv(t + 1, (t + 1) & 1); cpa_commit(); }

        const int k0 = t * 64;
        fp16* sKH = fsm + KVBASE + (t & 1) * KVSTG;
        fp16* sVH = sKH + 64 * FSTR;

        // ---- S = Qh Kh^T ----
        float s[8][4];
#pragma unroll
        for (int i = 0; i < 8; i++)
#pragma unroll
            for (int e = 0; e < 4; e++) s[i][e] = 0.f;

#pragma unroll
        for (int ks = 0; ks < 8; ks++) {
            uint32_t qf[4];
            int qa = (warp * 16 + (lane & 15)) * FSTR + ks * 16 + (lane >> 4) * 8;
            ldsm4(qf, smem_u32(&fsm[FQ + qa]));
            const int m = lane >> 3;
            uint32_t kb[4][4];
#pragma unroll
            for (int p = 0; p < 4; p++) {
                int ka = (p * 16 + (m >> 1) * 8 + (lane & 7)) * FSTR + ks * 16 + (m & 1) * 8;
                ldsm4(kb[p], smem_u32(&sKH[ka]));
            }
#pragma unroll
            for (int p = 0; p < 4; p++) {
                mma_fp16(s[p * 2],     qf, &kb[p][0]);
                mma_fp16(s[p * 2 + 1], qf, &kb[p][2]);
            }
        }

        // ---- scale + causal mask ----
        const int r0 = q0 + warp * 16 + (lane >> 2);
        const bool needmask = (t >= ntiles - 2);
#pragma unroll
        for (int nt = 0; nt < 8; nt++) {
#pragma unroll
            for (int e = 0; e < 4; e++) {
                float v = s[nt][e] * scale;
                if (needmask) {
                    int col = k0 + nt * 8 + (lane & 3) * 2 + (e & 1);
                    int row = r0 + ((e >> 1) << 3);
                    if (col > row) v = -1e30f;
                }
                s[nt][e] = v;
            }
        }

        // ---- online softmax ----
        float mx0 = -1e30f, mx1 = -1e30f;
#pragma unroll
        for (int nt = 0; nt < 8; nt++) {
            mx0 = fmaxf(mx0, fmaxf(s[nt][0], s[nt][1]));
            mx1 = fmaxf(mx1, fmaxf(s[nt][2], s[nt][3]));
        }
        mx0 = fmaxf(mx0, __shfl_xor_sync(0xffffffff, mx0, 1));
        mx0 = fmaxf(mx0, __shfl_xor_sync(0xffffffff, mx0, 2));
        mx1 = fmaxf(mx1, __shfl_xor_sync(0xffffffff, mx1, 1));
        mx1 = fmaxf(mx1, __shfl_xor_sync(0xffffffff, mx1, 2));
        float mn0 = fmaxf(mrow[0], mx0), mn1 = fmaxf(mrow[1], mx1);
        float f0 = __expf(mrow[0] - mn0), f1 = __expf(mrow[1] - mn1);

        float sum0 = 0.f, sum1 = 0.f;
#pragma unroll
        for (int nt = 0; nt < 8; nt++) {
            s[nt][0] = __expf(s[nt][0] - mn0);
            s[nt][1] = __expf(s[nt][1] - mn0);
            s[nt][2] = __expf(s[nt][2] - mn1);
            s[nt][3] = __expf(s[nt][3] - mn1);
            sum0 += s[nt][0] + s[nt][1];
            sum1 += s[nt][2] + s[nt][3];
        }
        sum0 += __shfl_xor_sync(0xffffffff, sum0, 1);
        sum0 += __shfl_xor_sync(0xffffffff, sum0, 2);
        sum1 += __shfl_xor_sync(0xffffffff, sum1, 1);
        sum1 += __shfl_xor_sync(0xffffffff, sum1, 2);
        lrow[0] = lrow[0] * f0 + sum0;
        lrow[1] = lrow[1] * f1 + sum1;
        mrow[0] = mn0;
        mrow[1] = mn1;

        // ---- rescale O ----
#pragma unroll
        for (int nt = 0; nt < 16; nt++) {
            o[nt][0] *= f0; o[nt][1] *= f0;
            o[nt][2] *= f1; o[nt][3] *= f1;
        }

        // ---- O += Ph Vh ----
#pragma unroll
        for (int ks = 0; ks < 4; ks++) {
            uint32_t ph[4];
#pragma unroll
            for (int half = 0; half < 2; half++) {
                int ti2 = 2 * ks + half;
                ph[2 * half]     = pack2h(__float2half_rn(s[ti2][0]), __float2half_rn(s[ti2][1]));
                ph[2 * half + 1] = pack2h(__float2half_rn(s[ti2][2]), __float2half_rn(s[ti2][3]));
            }
            const int m = lane >> 3;
#pragma unroll
            for (int pp = 0; pp < 8; pp++) {
                uint32_t vf[4];
                int va = (ks * 16 + (m & 1) * 8 + (lane & 7)) * FSTR + (pp * 2 + (m >> 1)) * 8;
                ldsm4t(vf, smem_u32(&sVH[va]));
                mma_fp16(o[pp * 2],     ph, &vf[0]);
                mma_fp16(o[pp * 2 + 1], ph, &vf[2]);
            }
        }
    }

    // ---- finalize: divide by l, write fp16 ----
    float inv0 = 1.f / lrow[0], inv1 = 1.f / lrow[1];
    const size_t tok0 = (size_t)(b * SEQ + q0 + warp * 16 + (lane >> 2));
#pragma unroll
    for (int nt = 0; nt < 16; nt++) {
        int col = h * HD + nt * 8 + (lane & 3) * 2;
        size_t a0 = tok0 * EMB + col;
        size_t a1 = (tok0 + 8) * EMB + col;
        *(uint32_t*)&Oh[a0] = pack2h(__float2half_rn(o[nt][0] * inv0),
                                     __float2half_rn(o[nt][1] * inv0));
        *(uint32_t*)&Oh[a1] = pack2h(__float2half_rn(o[nt][2] * inv1),
                                     __float2half_rn(o[nt][3] * inv1));
    }
}

// ============================================================================
// launch
// ============================================================================
extern "C" void kernel_launch(void* const* d_in, const int* in_sizes, int n_in,
                              void* d_out, int out_size)
{
    const float* x  = (const float*)d_in[0];
    const float* cs = (const float*)d_in[1];
    const float* sn = (const float*)d_in[2];
    const float* wq = (const float*)d_in[3];
    const float* wk = (const float*)d_in[4];
    const float* wv = (const float*)d_in[5];
    const float* wo = (const float*)d_in[6];
    float* out = (float*)d_out;

    fp16 *xh, *qh, *kh, *vh, *ath;
    fp16 *wqth, *wkth, *wvth, *woth;
    cudaGetSymbolAddress((void**)&xh,  g_xh);
    cudaGetSymbolAddress((void**)&qh,  g_qh);
    cudaGetSymbolAddress((void**)&kh,  g_kh);
    cudaGetSymbolAddress((void**)&vh,  g_vh);
    cudaGetSymbolAddress((void**)&ath, g_ath);
    cudaGetSymbolAddress((void**)&wqth, g_wqth);
    cudaGetSymbolAddress((void**)&wkth, g_wkth);
    cudaGetSymbolAddress((void**)&wvth, g_wvth);
    cudaGetSymbolAddress((void**)&woth, g_woth);

    const int fsmem = FSM_ELEMS * (int)sizeof(fp16);   // 104448 B
    cudaFuncSetAttribute(flash_mma, cudaFuncAttributeMaxDynamicSharedMemorySize, fsmem);
    cudaFuncSetAttribute(gemm_mma<256, OUT_H_ROPE>, cudaFuncAttributeMaxDynamicSharedMemorySize, GEMM_SMEM_256);
    cudaFuncSetAttribute(gemm_mma<256, OUT_F32>,    cudaFuncAttributeMaxDynamicSharedMemorySize, GEMM_SMEM_256);
    cudaFuncSetAttribute(gemm_mma<128, OUT_KV>,     cudaFuncAttributeMaxDynamicSharedMemorySize, GEMM_SMEM_128);

    const int M = BSZ * SEQ;   // 4096
    const int NKVD = NKV * HD; // 512

    // weight rounds, activation round
    wsplit_t_k<<<dim3(EMB / 32, EMB / 32),  dim3(32, 8)>>>(wq, wqth, EMB, EMB);
    wsplit_t_k<<<dim3(NKVD / 32, EMB / 32), dim3(32, 8)>>>(wk, wkth, EMB, NKVD);
    wsplit_t_k<<<dim3(NKVD / 32, EMB / 32), dim3(32, 8)>>>(wv, wvth, EMB, NKVD);
    wsplit_t_k<<<dim3(EMB / 32, EMB / 32),  dim3(32, 8)>>>(wo, woth, EMB, EMB);
    around_k<<<(M * EMB + 255) / 256, 256>>>(x, xh, M * EMB);

    // Q projection with fused rope epilogue (tensor cores)
    gemm_mma<256, OUT_H_ROPE><<<dim3(EMB / 256, M / 128), 256, GEMM_SMEM_256>>>(
        xh, wqth, nullptr, qh, nullptr, M, EMB, EMB, cs, sn);
    // K + V projections fused into one full-wave launch (z=0: K+rope, z=1: V)
    gemm_mma<128, OUT_KV><<<dim3(NKVD / 128, M / 128, 2), 256, GEMM_SMEM_128>>>(
        xh, wkth, wvth, kh, vh, M, NKVD, EMB, cs, sn);

    // attention (tensor cores), writes fp16 output
    flash_mma<<<dim3(SEQ / 128, NH, BSZ), 256, fsmem>>>(qh, kh, vh, ath);

    // out projection (tensor cores)
    gemm_mma<256, OUT_F32><<<dim3(EMB / 256, M / 128), 256, GEMM_SMEM_256>>>(
        ath, woth, nullptr, out, nullptr, M, EMB, EMB, nullptr, nullptr);
}